// round 1
// baseline (speedup 1.0000x reference)
#include <cuda_runtime.h>
#include <math.h>

#define VOL (128*128*128)          // 2^21 elements per volume
#define NB 8                        // batch*channels

// Scratch spectra (uninitialized device globals -> no runtime allocation)
__device__ float2 g_out_ft[(size_t)NB * VOL];
__device__ float2 g_tgt_ft[(size_t)NB * VOL];
// Accumulators: [0..519]=numerator, [520..1039]=out power, [1040..1559]=tgt power
// layout within each: shell*8 + bc, shells 0..64
__device__ float g_acc[3 * 65 * NB];

__device__ __forceinline__ float2 cmul(float2 a, float2 b) {
    return make_float2(fmaf(a.x, b.x, -a.y * b.y), fmaf(a.x, b.y, a.y * b.x));
}
__device__ __forceinline__ int rev7(int i) { return (int)(__brev((unsigned)i) >> 25); }

// Iterative radix-2 DIT FFT over 128 complex values in shared memory.
// 64 threads per line (t = 0..63). Input must be loaded bit-reversed.
// __syncthreads() inside: all threads of the block execute this uniformly.
__device__ __forceinline__ void fft_stages(float2* a, int t, const float2* tw) {
#pragma unroll
    for (int len = 2; len <= 128; len <<= 1) {
        int half = len >> 1;
        int pos = t & (half - 1);
        int i0 = 2 * t - pos;              // group*len + pos
        float2 w = tw[pos * (128 / len)];  // exp(-2*pi*i * pos / len)
        float2 u = a[i0];
        float2 v = cmul(a[i0 + half], w);
        a[i0]        = make_float2(u.x + v.x, u.y + v.y);
        a[i0 + half] = make_float2(u.x - v.x, u.y - v.y);
        __syncthreads();
    }
}

__device__ __forceinline__ void init_twiddles(float2* tw, int tid) {
    if (tid < 64) {
        float sv, cv;
        sincosf(-6.283185307179586f * (float)tid * (1.0f / 128.0f), &sv, &cv);
        tw[tid] = make_float2(cv, sv);
    }
}

// ---------------------------------------------------------------------------
// Pass 0: zero accumulators
__global__ void k_zero() {
    int i = blockIdx.x * blockDim.x + threadIdx.x;
    if (i < 3 * 65 * NB) g_acc[i] = 0.0f;
}

// ---------------------------------------------------------------------------
// Pass 1: x-axis FFT, real input -> complex spectra buffers.
// blockDim = (64, 8): 8 lines/block, line contiguous in memory.
__global__ void __launch_bounds__(512) k_fft_x(const float* __restrict__ a_in,
                                               const float* __restrict__ b_in) {
    __shared__ float2 tw[64];
    __shared__ float2 s[8][128];
    int t = threadIdx.x, l = threadIdx.y;
    int tid = l * 64 + t;
    init_twiddles(tw, tid);

    unsigned line = blockIdx.x * 8u + (unsigned)l;   // 0..262143 (16 vols * 128 * 128)
    unsigned vol  = line >> 14;                      // 0..15 (0..7 out, 8..15 tgt)
    unsigned zy   = line & 16383u;

    const float* src;
    float2* dst;
    if (vol < 8) {
        src = a_in     + ((size_t)vol * 16384 + zy) * 128;
        dst = g_out_ft + ((size_t)vol * 16384 + zy) * 128;
    } else {
        src = b_in     + ((size_t)(vol - 8) * 16384 + zy) * 128;
        dst = g_tgt_ft + ((size_t)(vol - 8) * 16384 + zy) * 128;
    }

    float v0 = src[t];
    float v1 = src[t + 64];
    s[l][rev7(t)]      = make_float2(v0, 0.0f);
    s[l][rev7(t + 64)] = make_float2(v1, 0.0f);
    __syncthreads();

    fft_stages(&s[l][0], t, tw);

    dst[t]      = s[l][t];
    dst[t + 64] = s[l][t + 64];
}

// ---------------------------------------------------------------------------
// Pass 2: y-axis FFT in place. blockDim = (16, 64): 16 consecutive-x lines/block
// so global accesses are 128B-contiguous across lanes.
__global__ void __launch_bounds__(1024) k_fft_y() {
    __shared__ float2 tw[64];
    __shared__ float2 s[16][129];   // +1 pad to break bank conflicts
    int lx = threadIdx.x, t = threadIdx.y;
    int tid = t * 16 + lx;
    init_twiddles(tw, tid);

    unsigned b   = blockIdx.x;            // 16 vols * 128 z * 8 xtiles = 16384
    unsigned xt  = b & 7u;
    unsigned z   = (b >> 3) & 127u;
    unsigned vol = b >> 10;

    float2* base = ((vol < 8) ? g_out_ft + (size_t)vol * VOL
                              : g_tgt_ft + (size_t)(vol - 8) * VOL)
                   + (size_t)z * 16384 + xt * 16 + lx;

    float2 e0 = base[(size_t)t * 128];
    float2 e1 = base[(size_t)(t + 64) * 128];
    s[lx][rev7(t)]      = e0;
    s[lx][rev7(t + 64)] = e1;
    __syncthreads();

    fft_stages(&s[lx][0], t, tw);

    base[(size_t)t * 128]        = s[lx][t];
    base[(size_t)(t + 64) * 128] = s[lx][t + 64];
}

// ---------------------------------------------------------------------------
// Pass 3: z-axis FFT for both out & tgt spectra of one batch element, fused
// with the radial-shell reduction (numerator, out power, tgt power).
__global__ void __launch_bounds__(1024) k_fft_z_reduce() {
    __shared__ float2 tw[64];
    __shared__ float2 so[16][129];
    __shared__ float2 st[16][129];
    __shared__ float  bins[65 * 3];
    int lx = threadIdx.x, t = threadIdx.y;
    int tid = t * 16 + lx;
    init_twiddles(tw, tid);
    if (tid < 65 * 3) bins[tid] = 0.0f;

    unsigned b  = blockIdx.x;             // 8 bc * 128 y * 8 xtiles = 8192
    unsigned xt = b & 7u;
    unsigned y  = (b >> 3) & 127u;
    unsigned bc = b >> 10;

    size_t off = (size_t)bc * VOL + (size_t)y * 128 + xt * 16 + lx;
    const float2* po = g_out_ft + off;
    const float2* pg = g_tgt_ft + off;

    float2 o0 = po[(size_t)t * 16384];
    float2 o1 = po[(size_t)(t + 64) * 16384];
    float2 g0 = pg[(size_t)t * 16384];
    float2 g1 = pg[(size_t)(t + 64) * 16384];
    so[lx][rev7(t)]      = o0;
    so[lx][rev7(t + 64)] = o1;
    st[lx][rev7(t)]      = g0;
    st[lx][rev7(t + 64)] = g1;
    __syncthreads();

    // Interleaved FFT over both lines (shares the per-stage barrier)
#pragma unroll
    for (int len = 2; len <= 128; len <<= 1) {
        int half = len >> 1;
        int pos = t & (half - 1);
        int i0 = 2 * t - pos;
        float2 w = tw[pos * (128 / len)];
        {
            float2* A = &so[lx][0];
            float2 u = A[i0];
            float2 v = cmul(A[i0 + half], w);
            A[i0]        = make_float2(u.x + v.x, u.y + v.y);
            A[i0 + half] = make_float2(u.x - v.x, u.y - v.y);
        }
        {
            float2* A = &st[lx][0];
            float2 u = A[i0];
            float2 v = cmul(A[i0 + half], w);
            A[i0]        = make_float2(u.x + v.x, u.y + v.y);
            A[i0 + half] = make_float2(u.x - v.x, u.y - v.y);
        }
        __syncthreads();
    }

    // Shell accumulation. Ortho norm: each F scaled by 1/sqrt(128^3);
    // products scaled by c2 = 128^-3 = 2^-21 (exact).
    const float c2 = 4.76837158203125e-7f;
    int fx = (int)(xt * 16 + lx); if (fx >= 64) fx -= 128;
    int fy = (int)y;              if (fy >= 64) fy -= 128;
    int fxy2 = fx * fx + fy * fy;

#pragma unroll
    for (int h = 0; h < 2; h++) {
        int kz = t + 64 * h;
        int fz = (kz < 64) ? kz : kz - 128;
        int r2 = fz * fz + fxy2;
        int sh = (int)sqrtf((float)r2);   // exact truncation for these ints
        if (sh <= 64) {
            float2 o = so[lx][kz];
            float2 g = st[lx][kz];
            atomicAdd(&bins[sh * 3 + 0], c2 * (o.x * g.x + o.y * g.y));
            atomicAdd(&bins[sh * 3 + 1], c2 * (o.x * o.x + o.y * o.y));
            atomicAdd(&bins[sh * 3 + 2], c2 * (g.x * g.x + g.y * g.y));
        }
    }
    __syncthreads();

    if (tid < 65 * 3) {
        int sh = tid / 3, c3 = tid % 3;
        atomicAdd(&g_acc[c3 * 520 + sh * 8 + bc], bins[tid]);
    }
}

// ---------------------------------------------------------------------------
// Pass 4: FSC + masked mean -> scalar loss.
__global__ void k_final(float* __restrict__ out) {
    __shared__ float red[NB];
    int bc = threadIdx.x;
    if (bc < NB) {
        float acc = 0.0f;
        for (int s = 1; s <= 64; s++) {
            float n   = g_acc[0 * 520 + s * 8 + bc];
            float pwo = g_acc[1 * 520 + s * 8 + bc];
            float pwt = g_acc[2 * 520 + s * 8 + bc];
            float f = n / sqrtf(pwo * pwt + 1e-6f);
            f = fminf(1.0f, fmaxf(-1.0f, f));
            acc += f;
        }
        red[bc] = 1.0f - acc * (1.0f / 64.0f);
    }
    __syncthreads();
    if (bc == 0) {
        float m = 0.0f;
#pragma unroll
        for (int i = 0; i < NB; i++) m += red[i];
        out[0] = m * (1.0f / (float)NB);
    }
}

// ---------------------------------------------------------------------------
extern "C" void kernel_launch(void* const* d_in, const int* in_sizes, int n_in,
                              void* d_out, int out_size) {
    const float* model_output = (const float*)d_in[0];
    const float* target       = (const float*)d_in[1];

    k_zero<<<7, 256>>>();
    k_fft_x<<<(16 * 128 * 128) / 8, dim3(64, 8)>>>(model_output, target);
    k_fft_y<<<16 * 128 * 8, dim3(16, 64)>>>();
    k_fft_z_reduce<<<8 * 128 * 8, dim3(16, 64)>>>();
    k_final<<<1, NB>>>((float*)d_out);
}

// round 2
// speedup vs baseline: 1.9031x; 1.9031x over previous
#include <cuda_runtime.h>
#include <cuda_fp16.h>
#include <math.h>

#define VOL (128*128*128)          // 2^21 elements per volume
#define NB 8                        // batch*channels

// fp16 spectrum scratch: vols 0..7 = model_output, 8..15 = target.
// Layout: [vol][kx][z][y]  (y contiguous)  => 16 * 2M * 4B = 134MB
__device__ __half2 g_ft[(size_t)16 * VOL];
// Accumulators: c3*520 + shell*8 + bc ; c3: 0=num, 1=out power, 2=tgt power
__device__ float g_acc[3 * 65 * NB];

__device__ __forceinline__ float2 cmul(float2 a, float2 b) {
    return make_float2(fmaf(a.x, b.x, -a.y * b.y), fmaf(a.x, b.y, a.y * b.x));
}
__device__ __forceinline__ int rev5(int i) { return (int)(__brev((unsigned)i) >> 27); }

// ---------------------------------------------------------------------------
// 128-point forward FFT within one warp. Each lane holds 4 complex values.
// Element (natural/output) index i = 4*lane + r. Input must be loaded
// bit-reversed: v[r] = src[rev5(lane) + {0,64,32,96}[r]].
// tw[k] = exp(-2*pi*i*k/128), k = 0..63 (shared).
__device__ __forceinline__ void warp_fft128(float2 v[4], int lane, const float2* tw) {
    float2 t;
    // stage len=2 : pairs (0,1),(2,3), w=1
    t = v[1]; v[1] = make_float2(v[0].x - t.x, v[0].y - t.y);
              v[0] = make_float2(v[0].x + t.x, v[0].y + t.y);
    t = v[3]; v[3] = make_float2(v[2].x - t.x, v[2].y - t.y);
              v[2] = make_float2(v[2].x + t.x, v[2].y + t.y);
    // stage len=4 : (0,2) w=1 ; (1,3) w=-i
    t = v[2]; v[2] = make_float2(v[0].x - t.x, v[0].y - t.y);
              v[0] = make_float2(v[0].x + t.x, v[0].y + t.y);
    t = make_float2(v[3].y, -v[3].x);                      // -i * v3
    v[3] = make_float2(v[1].x - t.x, v[1].y - t.y);
    v[1] = make_float2(v[1].x + t.x, v[1].y + t.y);
    // 5 shuffle stages: half = 4,8,16,32,64 ; lane xor mask m = half/4
#pragma unroll
    for (int s = 0; s < 5; s++) {
        int m = 1 << s;
        bool hi = (lane & m) != 0;
        float sgn = hi ? -1.0f : 1.0f;
#pragma unroll
        for (int r = 0; r < 4; r++) {
            int pos = ((lane & (m - 1)) << 2) | r;         // i mod half
            float2 w = tw[pos << (4 - s)];                 // pos * (64/half)
            float2 mine = v[r];
            float2 oth;
            oth.x = __shfl_xor_sync(0xffffffffu, mine.x, m);
            oth.y = __shfl_xor_sync(0xffffffffu, mine.y, m);
            float2 u  = hi ? oth : mine;
            float2 vv = hi ? mine : oth;
            float2 wv = cmul(w, vv);
            v[r] = make_float2(fmaf(sgn, wv.x, u.x), fmaf(sgn, wv.y, u.y));
        }
    }
}

__device__ __forceinline__ void init_tw(float2* tw, int tid) {
    if (tid < 64) {
        float sv, cv;
        sincosf(-6.283185307179586f * (float)tid * (1.0f / 128.0f), &sv, &cv);
        tw[tid] = make_float2(cv, sv);
    }
}

// ---------------------------------------------------------------------------
__global__ void k_zero() {
    int i = blockIdx.x * blockDim.x + threadIdx.x;
    if (i < 3 * 65 * NB) g_acc[i] = 0.0f;
}

// ---------------------------------------------------------------------------
// Pass 1: x-axis FFT (register/shuffle), fp16 output transposed to
// [vol][kx][z][y] through an smem tile so global writes stay coalesced.
// Block: 1024 threads = 32 warps; warp w handles y = ytile*32 + w, fixed z.
__global__ void __launch_bounds__(1024) k_fft_x(const float* __restrict__ a_in,
                                                const float* __restrict__ b_in) {
    __shared__ float2 tw[64];
    __shared__ __half2 tile[32][129];     // [y_local][kx], pitch 129 (conflict-free)
    int tid = threadIdx.x;
    int lane = tid & 31, w = tid >> 5;
    init_tw(tw, tid);

    unsigned b = blockIdx.x;              // 16 vols * 128 z * 4 ytiles = 8192
    unsigned ytile = b & 3u;
    unsigned z     = (b >> 2) & 127u;
    unsigned vol   = b >> 9;

    const float* src = ((vol < 8) ? a_in + (size_t)vol * VOL
                                  : b_in + (size_t)(vol - 8) * VOL)
                       + (size_t)z * 16384 + (size_t)(ytile * 32 + w) * 128;
    __syncthreads();                      // tw ready

    int rb = rev5(lane);
    float2 v[4];
    v[0] = make_float2(src[rb],      0.0f);
    v[1] = make_float2(src[rb + 64], 0.0f);
    v[2] = make_float2(src[rb + 32], 0.0f);
    v[3] = make_float2(src[rb + 96], 0.0f);
    warp_fft128(v, lane, tw);

    const float sc = 0.08838834764831845f;    // 1/sqrt(128)
#pragma unroll
    for (int r = 0; r < 4; r++)
        tile[w][4 * lane + r] = __float22half2_rn(make_float2(v[r].x * sc, v[r].y * sc));
    __syncthreads();

    // transposed write-out: lanes sweep consecutive y -> 128B coalesced stores
    size_t base = ((size_t)vol * 128) * 16384 + (size_t)z * 128 + ytile * 32 + lane;
#pragma unroll
    for (int xi = 0; xi < 4; xi++) {
        int kx = w * 4 + xi;
        g_ft[base + (size_t)kx * 16384] = tile[lane][kx];
    }
}

// ---------------------------------------------------------------------------
// Pass 2 (fused): for each (bc, kx) load both (z,y) planes into smem (fp16),
// y-FFT all rows, z-FFT all columns, shell-reduce into per-warp bins.
// Dynamic smem: planeO(66048) + planeT(66048) + bins(32*196*4) + tw(512)
#define SMEM2 (2 * 128 * 129 * 4 + 32 * 196 * 4 + 64 * 8)

__global__ void __launch_bounds__(1024, 1) k_fft_yz_reduce() {
    extern __shared__ unsigned char smem_raw[];
    __half2* pO  = (__half2*)smem_raw;                 // [z][y] pitch 129
    __half2* pT  = pO + 128 * 129;
    float*  bins = (float*)(pT + 128 * 129);           // [warp][196]
    float2* tw   = (float2*)(bins + 32 * 196);

    int tid = threadIdx.x, lane = tid & 31, w = tid >> 5;
    init_tw(tw, tid);
    for (int i = tid; i < 32 * 196; i += 1024) bins[i] = 0.0f;

    unsigned kx = blockIdx.x & 127u;
    unsigned bc = blockIdx.x >> 7;
    const __half2* gO = g_ft + ((size_t)bc * 128 + kx) * 16384;
    const __half2* gT = g_ft + ((size_t)(bc + 8) * 128 + kx) * 16384;

    // load planes (coalesced global, padded smem rows)
#pragma unroll
    for (int i = 0; i < 16; i++) {
        int idx = tid + i * 1024;
        int z = idx >> 7, y = idx & 127;
        pO[z * 129 + y] = gO[idx];
        pT[z * 129 + y] = gT[idx];
    }
    __syncthreads();

    int rb = rev5(lane);
    const float sc = 0.08838834764831845f;

    // y-FFT: 256 rows (128 O + 128 T), 8 rows per warp
#pragma unroll
    for (int i = 0; i < 8; i++) {
        int row = w + i * 32;
        __half2* rowp = ((row < 128) ? pO : pT) + (row & 127) * 129;
        float2 v[4];
        v[0] = __half22float2(rowp[rb]);
        v[1] = __half22float2(rowp[rb + 64]);
        v[2] = __half22float2(rowp[rb + 32]);
        v[3] = __half22float2(rowp[rb + 96]);
        warp_fft128(v, lane, tw);
#pragma unroll
        for (int r = 0; r < 4; r++)
            rowp[4 * lane + r] = __float22half2_rn(make_float2(v[r].x * sc, v[r].y * sc));
    }
    __syncthreads();

    // z-FFT + shell reduction: 4 y-columns per warp, both spectra per column
    int fx = (int)kx; if (fx >= 64) fx -= 128;
    float* mybins = bins + w * 196;
    const float c2 = 0.0078125f;   // remaining 1/128 of ortho norm on products
#pragma unroll
    for (int i = 0; i < 4; i++) {
        int y = w + i * 32;
        float2 vo[4], vt[4];
        vo[0] = __half22float2(pO[ rb       * 129 + y]);
        vo[1] = __half22float2(pO[(rb + 64) * 129 + y]);
        vo[2] = __half22float2(pO[(rb + 32) * 129 + y]);
        vo[3] = __half22float2(pO[(rb + 96) * 129 + y]);
        warp_fft128(vo, lane, tw);
        vt[0] = __half22float2(pT[ rb       * 129 + y]);
        vt[1] = __half22float2(pT[(rb + 64) * 129 + y]);
        vt[2] = __half22float2(pT[(rb + 32) * 129 + y]);
        vt[3] = __half22float2(pT[(rb + 96) * 129 + y]);
        warp_fft128(vt, lane, tw);

        int fy = y; if (fy >= 64) fy -= 128;
        int fxy2 = fx * fx + fy * fy;
#pragma unroll
        for (int r = 0; r < 4; r++) {
            int kz = 4 * lane + r;
            int fz = (kz < 64) ? kz : kz - 128;
            int r2 = fz * fz + fxy2;
            int sh = (int)sqrtf((float)r2);        // exact truncation for these ints
            if (sh <= 64) {
                float2 o = vo[r], g = vt[r];
                atomicAdd(&mybins[sh * 3 + 0], c2 * (o.x * g.x + o.y * g.y));
                atomicAdd(&mybins[sh * 3 + 1], c2 * (o.x * o.x + o.y * o.y));
                atomicAdd(&mybins[sh * 3 + 2], c2 * (g.x * g.x + g.y * g.y));
            }
        }
    }
    __syncthreads();

    // fold per-warp bins -> global accumulators
    if (tid < 195) {
        float s = 0.0f;
#pragma unroll
        for (int ww = 0; ww < 32; ww++) s += bins[ww * 196 + tid];
        int sh = tid / 3, c3 = tid % 3;
        atomicAdd(&g_acc[c3 * 520 + sh * 8 + bc], s);
    }
}

// ---------------------------------------------------------------------------
__global__ void k_final(float* __restrict__ out) {
    __shared__ float red[NB];
    int bc = threadIdx.x;
    if (bc < NB) {
        float acc = 0.0f;
        for (int s = 1; s <= 64; s++) {
            float n   = g_acc[0 * 520 + s * 8 + bc];
            float pwo = g_acc[1 * 520 + s * 8 + bc];
            float pwt = g_acc[2 * 520 + s * 8 + bc];
            float f = n / sqrtf(pwo * pwt + 1e-6f);
            f = fminf(1.0f, fmaxf(-1.0f, f));
            acc += f;
        }
        red[bc] = 1.0f - acc * (1.0f / 64.0f);
    }
    __syncthreads();
    if (bc == 0) {
        float m = 0.0f;
#pragma unroll
        for (int i = 0; i < NB; i++) m += red[i];
        out[0] = m * (1.0f / (float)NB);
    }
}

// ---------------------------------------------------------------------------
extern "C" void kernel_launch(void* const* d_in, const int* in_sizes, int n_in,
                              void* d_out, int out_size) {
    const float* model_output = (const float*)d_in[0];
    const float* target       = (const float*)d_in[1];

    cudaFuncSetAttribute(k_fft_yz_reduce,
                         cudaFuncAttributeMaxDynamicSharedMemorySize, SMEM2);

    k_zero<<<7, 256>>>();
    k_fft_x<<<16 * 128 * 4, 1024>>>(model_output, target);
    k_fft_yz_reduce<<<8 * 128, 1024, SMEM2>>>();
    k_final<<<1, NB>>>((float*)d_out);
}

// round 3
// speedup vs baseline: 2.5293x; 1.3290x over previous
#include <cuda_runtime.h>
#include <cuda_fp16.h>
#include <math.h>

#define VOL (128*128*128)          // 2^21
#define NB 8                        // batch*channels

// Packed spectra FFT(o + i*t): [vol][kx][z][y], fp16 complex => 67MB
__device__ __half2 g_ft[(size_t)NB * VOL];
// Accumulators: c3*520 + shell*8 + bc ; c3: 0=num, 1=out power, 2=tgt power
__device__ float g_acc[3 * 65 * NB];
__device__ unsigned g_done;        // zero-initialized; restored to 0 each launch

__device__ __forceinline__ float2 cmul(float2 a, float2 b) {
    return make_float2(fmaf(a.x, b.x, -a.y * b.y), fmaf(a.x, b.y, a.y * b.x));
}
__device__ __forceinline__ int rev5(int i) { return (int)(__brev((unsigned)i) >> 27); }

// ---------------------------------------------------------------------------
// 128-point forward FFT within one warp; 4 complex values per lane.
// Output (natural) index i = 4*lane + r. Input loaded bit-reversed:
// v[r] = src[rev5(lane) + {0,64,32,96}[r]].  tw[k]=exp(-2*pi*i*k/128), k<64.
__device__ __forceinline__ void warp_fft128(float2 v[4], int lane, const float2* tw) {
    float2 t;
    // len=2
    t = v[1]; v[1] = make_float2(v[0].x - t.x, v[0].y - t.y);
              v[0] = make_float2(v[0].x + t.x, v[0].y + t.y);
    t = v[3]; v[3] = make_float2(v[2].x - t.x, v[2].y - t.y);
              v[2] = make_float2(v[2].x + t.x, v[2].y + t.y);
    // len=4 : (0,2) w=1 ; (1,3) w=-i
    t = v[2]; v[2] = make_float2(v[0].x - t.x, v[0].y - t.y);
              v[0] = make_float2(v[0].x + t.x, v[0].y + t.y);
    t = make_float2(v[3].y, -v[3].x);
    v[3] = make_float2(v[1].x - t.x, v[1].y - t.y);
    v[1] = make_float2(v[1].x + t.x, v[1].y + t.y);
    // 5 shuffle stages
#pragma unroll
    for (int s = 0; s < 5; s++) {
        int m = 1 << s;
        bool hi = (lane & m) != 0;
        float sgn = hi ? -1.0f : 1.0f;
#pragma unroll
        for (int r = 0; r < 4; r++) {
            int pos = ((lane & (m - 1)) << 2) | r;
            float2 w = tw[pos << (4 - s)];
            float2 mine = v[r];
            float2 oth;
            oth.x = __shfl_xor_sync(0xffffffffu, mine.x, m);
            oth.y = __shfl_xor_sync(0xffffffffu, mine.y, m);
            float2 u  = hi ? oth : mine;
            float2 vv = hi ? mine : oth;
            float2 wv = cmul(w, vv);
            v[r] = make_float2(fmaf(sgn, wv.x, u.x), fmaf(sgn, wv.y, u.y));
        }
    }
}

__device__ __forceinline__ void init_tw(float2* tw, int tid) {
    if (tid < 64) {
        float sv, cv;
        sincosf(-6.283185307179586f * (float)tid * (1.0f / 128.0f), &sv, &cv);
        tw[tid] = make_float2(cv, sv);
    }
}

// ---------------------------------------------------------------------------
// Pass 1: pack P = o + i*t, x-FFT, write fp16 transposed to [vol][kx][z][y].
__global__ void __launch_bounds__(1024) k_fft_x(const float* __restrict__ a_in,
                                                const float* __restrict__ b_in) {
    __shared__ float2 tw[64];
    __shared__ __half2 tile[32][129];
    int tid = threadIdx.x, lane = tid & 31, w = tid >> 5;
    init_tw(tw, tid);

    unsigned b = blockIdx.x;              // 8 vols * 128 z * 4 ytiles = 4096
    unsigned ytile = b & 3u;
    unsigned z     = (b >> 2) & 127u;
    unsigned vol   = b >> 9;

    size_t off = (size_t)vol * VOL + (size_t)z * 16384 + (size_t)(ytile * 32 + w) * 128;
    const float* so = a_in + off;
    const float* st = b_in + off;
    __syncthreads();                      // tw ready

    int rb = rev5(lane);
    float2 v[4];
    v[0] = make_float2(so[rb],      st[rb]);
    v[1] = make_float2(so[rb + 64], st[rb + 64]);
    v[2] = make_float2(so[rb + 32], st[rb + 32]);
    v[3] = make_float2(so[rb + 96], st[rb + 96]);
    warp_fft128(v, lane, tw);

    const float sc = 0.08838834764831845f;    // 1/sqrt(128)
#pragma unroll
    for (int r = 0; r < 4; r++)
        tile[w][4 * lane + r] = __float22half2_rn(make_float2(v[r].x * sc, v[r].y * sc));
    __syncthreads();

    size_t base = (size_t)vol * VOL + (size_t)z * 128 + ytile * 32 + lane;
#pragma unroll
    for (int xi = 0; xi < 4; xi++) {
        int kx = w * 4 + xi;
        g_ft[base + (size_t)kx * 16384] = tile[lane][kx];
    }
}

// ---------------------------------------------------------------------------
// Pass 2: per (bc, kx-pair) load plane(s), y-FFT, z-FFT, Hermitian split,
// shell-reduce. Last block finishes the FSC loss and resets global state.
#define SMEM2 (2 * 128 * 129 * 4 + 32 * 196 * 4 + 64 * 8)

__global__ void __launch_bounds__(1024, 1) k_fft_yz_reduce(float* __restrict__ out) {
    extern __shared__ unsigned char smem_raw[];
    __half2* pA   = (__half2*)smem_raw;               // plane kx1 [z][y] pitch 129
    __half2* pBs  = pA + 128 * 129;                   // plane kx2
    float*   bins = (float*)(pBs + 128 * 129);        // [warp][196]
    float2*  tw   = (float2*)(bins + 32 * 196);
    __shared__ bool s_last;
    __shared__ float red[NB];

    int tid = threadIdx.x, lane = tid & 31, w = tid >> 5;
    init_tw(tw, tid);
    for (int i = tid; i < 32 * 196; i += 1024) bins[i] = 0.0f;

    unsigned bc  = blockIdx.x / 65;
    unsigned kx1 = blockIdx.x % 65;                   // 0..64
    unsigned kx2 = (128u - kx1) & 127u;
    bool dual = (kx2 != kx1);
    __half2* pB = dual ? pBs : pA;

    const __half2* gA = g_ft + ((size_t)bc * 128 + kx1) * 16384;
    const __half2* gB = g_ft + ((size_t)bc * 128 + kx2) * 16384;
#pragma unroll
    for (int i = 0; i < 16; i++) {
        int idx = tid + i * 1024;
        int z = idx >> 7, y = idx & 127;
        pA[z * 129 + y] = gA[idx];
        if (dual) pBs[z * 129 + y] = gB[idx];
    }
    __syncthreads();

    int rb = rev5(lane);
    const float sc = 0.08838834764831845f;
    int nplanes = dual ? 2 : 1;

    // y-FFT: 128 rows per plane, 4 per warp
    for (int p = 0; p < nplanes; p++) {
        __half2* pl = p ? pBs : pA;
#pragma unroll
        for (int i = 0; i < 4; i++) {
            __half2* rowp = pl + (w + 32 * i) * 129;
            float2 v[4];
            v[0] = __half22float2(rowp[rb]);
            v[1] = __half22float2(rowp[rb + 64]);
            v[2] = __half22float2(rowp[rb + 32]);
            v[3] = __half22float2(rowp[rb + 96]);
            warp_fft128(v, lane, tw);
#pragma unroll
            for (int r = 0; r < 4; r++)
                rowp[4 * lane + r] = __float22half2_rn(make_float2(v[r].x * sc, v[r].y * sc));
        }
    }
    __syncthreads();

    // z-FFT: 128 columns per plane, 4 per warp (in place, column-owned)
    for (int p = 0; p < nplanes; p++) {
        __half2* pl = p ? pBs : pA;
#pragma unroll
        for (int i = 0; i < 4; i++) {
            int y = w + 32 * i;
            float2 v[4];
            v[0] = __half22float2(pl[ rb       * 129 + y]);
            v[1] = __half22float2(pl[(rb + 64) * 129 + y]);
            v[2] = __half22float2(pl[(rb + 32) * 129 + y]);
            v[3] = __half22float2(pl[(rb + 96) * 129 + y]);
            warp_fft128(v, lane, tw);
#pragma unroll
            for (int r = 0; r < 4; r++)
                pl[(4 * lane + r) * 129 + y] =
                    __float22half2_rn(make_float2(v[r].x * sc, v[r].y * sc));
        }
    }
    __syncthreads();

    // Hermitian split + shell reduction over plane kx1 (factor 2 covers kx2).
    // O = (F[k]+conj(F[-k]))/2 ; T = (F[k]-conj(F[-k]))/(2i). Halves folded
    // into cfac: products * 1/4, *2 if dual.
    int fx = (int)kx1; if (fx >= 64) fx -= 128;
    float cfac = dual ? 0.5f : 0.25f;
    float* mybins = bins + w * 196;
#pragma unroll
    for (int i = 0; i < 16; i++) {
        int idx = tid + i * 1024;
        int z = idx >> 7, y = idx & 127;
        int fy = (y >= 64) ? y - 128 : y;
        int fz = (z >= 64) ? z - 128 : z;
        int r2 = fx * fx + fy * fy + fz * fz;
        int sh = (int)sqrtf((float)r2);           // exact truncation here
        if (sh <= 64) {
            int mz = (128 - z) & 127, my = (128 - y) & 127;
            float2 F  = __half22float2(pA[z * 129 + y]);
            float2 Fm = __half22float2(pB[mz * 129 + my]);
            float Ox = F.x + Fm.x, Oy = F.y - Fm.y;   // 2*O
            float Tx = F.y + Fm.y, Ty = Fm.x - F.x;   // 2*T
            atomicAdd(&mybins[sh * 3 + 0], cfac * (Ox * Tx + Oy * Ty));
            atomicAdd(&mybins[sh * 3 + 1], cfac * (Ox * Ox + Oy * Oy));
            atomicAdd(&mybins[sh * 3 + 2], cfac * (Tx * Tx + Ty * Ty));
        }
    }
    __syncthreads();

    // fold per-warp bins -> global accumulators
    if (tid < 195) {
        float s = 0.0f;
#pragma unroll
        for (int ww = 0; ww < 32; ww++) s += bins[ww * 196 + tid];
        int sh = tid / 3, c3 = tid % 3;
        atomicAdd(&g_acc[c3 * 520 + sh * 8 + bc], s);
    }
    __syncthreads();

    // completion counter; last block computes the loss and resets state
    if (tid == 0) {
        __threadfence();
        unsigned old = atomicAdd(&g_done, 1u);
        s_last = (old == gridDim.x - 1);
    }
    __syncthreads();
    if (!s_last) return;

    float* sacc = bins;   // reuse smem
    for (int i = tid; i < 3 * 65 * NB; i += 1024)
        sacc[i] = atomicExch(&g_acc[i], 0.0f);    // read + reset for next replay
    __syncthreads();

    if (tid < NB) {
        float acc = 0.0f;
        for (int s = 1; s <= 64; s++) {
            float n  = sacc[0 * 520 + s * 8 + tid];
            float po = sacc[1 * 520 + s * 8 + tid];
            float pt = sacc[2 * 520 + s * 8 + tid];
            float f = n / sqrtf(po * pt + 1e-6f);
            acc += fminf(1.0f, fmaxf(-1.0f, f));
        }
        red[tid] = 1.0f - acc * (1.0f / 64.0f);
    }
    __syncthreads();
    if (tid == 0) {
        float m = 0.0f;
#pragma unroll
        for (int i = 0; i < NB; i++) m += red[i];
        out[0] = m * (1.0f / (float)NB);
        atomicExch(&g_done, 0u);
    }
}

// ---------------------------------------------------------------------------
extern "C" void kernel_launch(void* const* d_in, const int* in_sizes, int n_in,
                              void* d_out, int out_size) {
    const float* model_output = (const float*)d_in[0];
    const float* target       = (const float*)d_in[1];

    cudaFuncSetAttribute(k_fft_yz_reduce,
                         cudaFuncAttributeMaxDynamicSharedMemorySize, SMEM2);

    k_fft_x<<<8 * 128 * 4, 1024>>>(model_output, target);
    k_fft_yz_reduce<<<8 * 65, 1024, SMEM2>>>((float*)d_out);
}